// round 13
// baseline (speedup 1.0000x reference)
#include <cuda_runtime.h>
#include <cuda_fp16.h>
#include <math.h>
#include <stdint.h>

#define NA 500000
#define NC 250000
#define NE 1000000
#define NB 2048
#define DD 256
#define NH 4

// ---------------- scratch ----------------
__device__ __align__(16) __half g_hxh[(size_t)NC * DD];
__device__ __align__(16) __half g_wph[DD * DD];       // Wp^T fp16 [N][K]
__device__ __align__(16) __half g_w1h[NH * 128 * 64]; // W1^T fp16 [h][n][k]
__device__ int      g_cb[NC];
__device__ int      g_cnt[NC];
__device__ int      g_off[NC + 1];
__device__ int      g_fill[NC];
__device__ int      g_csr[NE];
__device__ int      g_part[256];
__device__ float    g_score[NC * NH];
__device__ unsigned g_mxu[NB * NH];
__device__ float    g_den[NB * NH];
__device__ int      g_is32;

// ---------------- PTX helpers ----------------
__device__ __forceinline__ void mma_f16(float* c, const uint32_t* a, const uint32_t* b) {
    asm volatile(
        "mma.sync.aligned.m16n8k16.row.col.f32.f16.f16.f32 "
        "{%0,%1,%2,%3}, {%4,%5,%6,%7}, {%8,%9}, {%0,%1,%2,%3};"
        : "+f"(c[0]), "+f"(c[1]), "+f"(c[2]), "+f"(c[3])
        : "r"(a[0]), "r"(a[1]), "r"(a[2]), "r"(a[3]), "r"(b[0]), "r"(b[1]));
}
__device__ __forceinline__ void ldsm_x4(uint32_t* r, uint32_t saddr) {
    asm volatile("ldmatrix.sync.aligned.m8n8.x4.shared.b16 {%0,%1,%2,%3}, [%4];"
        : "=r"(r[0]), "=r"(r[1]), "=r"(r[2]), "=r"(r[3]) : "r"(saddr));
}
__device__ __forceinline__ uint32_t smem_u32(const void* p) {
    uint32_t a;
    asm("{ .reg .u64 t; cvta.to.shared.u64 t, %1; cvt.u32.u64 %0, t; }" : "=r"(a) : "l"(p));
    return a;
}
__device__ __forceinline__ void cp_async16(uint32_t sa, const void* g) {
    asm volatile("cp.async.cg.shared.global [%0], [%1], 16;" :: "r"(sa), "l"(g));
}
__device__ __forceinline__ void cp_commit() { asm volatile("cp.async.commit_group;"); }
template <int N>
__device__ __forceinline__ void cp_wait() { asm volatile("cp.async.wait_group %0;" :: "n"(N)); }

__device__ __forceinline__ unsigned f2u_ord(float f) {
    unsigned u = __float_as_uint(f);
    return (u & 0x80000000u) ? ~u : (u | 0x80000000u);
}
__device__ __forceinline__ float u2f_ord(unsigned u) {
    return (u & 0x80000000u) ? __uint_as_float(u ^ 0x80000000u) : __uint_as_float(~u);
}
__device__ __forceinline__ int clampi(int v, int lo, int hi) {
    return v < lo ? lo : (v > hi ? hi : v);
}
__device__ __forceinline__ uint32_t pack_split(float f, __half* lo) {
    __half h = __float2half(f);
    *lo = __float2half(f - __half2float(h));
    return (uint32_t)*(const uint16_t*)&h;
}
__device__ __forceinline__ int idx_at(const void* p, int i) {
    return g_is32 ? ((const int*)p)[i] : (int)(((const long long*)p)[i]);
}

// ---------------- init (+detect in block 0) ----------------
__global__ void k_initdet(float* __restrict__ drug, const long long* __restrict__ a2c) {
    int i = blockIdx.x * blockDim.x + threadIdx.x;
    if (blockIdx.x == 0) {
        __shared__ int s;
        if (threadIdx.x == 0) s = 0;
        __syncthreads();
        long long v = a2c[threadIdx.x];
        if (v < 0 || v >= 0x80000000LL) atomicOr(&s, 1);
        __syncthreads();
        if (threadIdx.x == 0) g_is32 = s;
    }
    if (i < NB * DD) drug[i] = 0.f;
    if (i < NC) { g_cnt[i] = 0; g_fill[i] = 0; }
    if (i < NB * NH) { g_den[i] = 0.f; g_mxu[i] = f2u_ord(-3.0e38f); }
}

// ---------------- histogram + cb convert ----------------
__global__ void k_hist_cvt(const void* __restrict__ a2c, const void* __restrict__ cb) {
    int i = blockIdx.x * blockDim.x + threadIdx.x;
    if (i < NC) g_cb[i] = clampi(idx_at(cb, i), 0, NB - 1);
    if (i < NE) atomicAdd(&g_cnt[clampi(idx_at(a2c, NE + i), 0, NC - 1)], 1);
}

// ---------------- scan ----------------
__global__ void k_scan_a() {
    __shared__ int sums[256];
    int tid = threadIdx.x;
    int base = blockIdx.x * 2048 + tid * 8;
    int pre[8]; int s = 0;
#pragma unroll
    for (int j = 0; j < 8; j++) {
        int idx = base + j;
        int v = (idx < NC) ? g_cnt[idx] : 0;
        pre[j] = s; s += v;
    }
    sums[tid] = s;
    __syncthreads();
    for (int off = 1; off < 256; off <<= 1) {
        int t = (tid >= off) ? sums[tid - off] : 0;
        __syncthreads();
        sums[tid] += t;
        __syncthreads();
    }
    int excl = (tid == 0) ? 0 : sums[tid - 1];
#pragma unroll
    for (int j = 0; j < 8; j++) {
        int idx = base + j;
        if (idx < NC) g_off[idx] = excl + pre[j];
    }
    if (tid == 255) g_part[blockIdx.x] = sums[255];
}
__global__ void k_scan_b(int nb) {
    if (threadIdx.x == 0) {
        int s = 0;
        for (int i = 0; i < nb; i++) { int t = g_part[i]; g_part[i] = s; s += t; }
    }
}
__global__ void k_scan_c() {
    int i = blockIdx.x * blockDim.x + threadIdx.x;
    if (i < NC) g_off[i] += g_part[i >> 11];
}

// ---------------- CSR fill ----------------
__global__ void k_fill(const void* __restrict__ a2c) {
    int i = blockIdx.x * blockDim.x + threadIdx.x;
    if (i >= NE) return;
    int c = clampi(idx_at(a2c, NE + i), 0, NC - 1);
    int r = clampi(idx_at(a2c, i), 0, NA - 1);
    int p = g_off[c] + atomicAdd(&g_fill[c], 1);
    if (p >= 0 && p < NE) g_csr[p] = r;
}

// ---------------- gather + mean -> fp16 (4 cliques / 256-thread block) ----------------
__global__ void __launch_bounds__(256) k_agg(const float* __restrict__ x) {
    int c = blockIdx.x * 4 + (threadIdx.x >> 6);
    if (c >= NC) return;
    int t = threadIdx.x & 63;
    int deg = g_cnt[c];
    int st  = g_off[c];
    float4 acc = make_float4(0.f, 0.f, 0.f, 0.f);
    int e = 0;
    for (; e + 2 <= deg; e += 2) {
        int r0 = g_csr[st + e], r1 = g_csr[st + e + 1];
        float4 a = ((const float4*)(x + (size_t)r0 * DD))[t];
        float4 b = ((const float4*)(x + (size_t)r1 * DD))[t];
        acc.x += a.x + b.x; acc.y += a.y + b.y;
        acc.z += a.z + b.z; acc.w += a.w + b.w;
    }
    if (e < deg) {
        int r0 = g_csr[st + e];
        float4 a = ((const float4*)(x + (size_t)r0 * DD))[t];
        acc.x += a.x; acc.y += a.y; acc.z += a.z; acc.w += a.w;
    }
    float inv = 1.f / (float)max(deg, 1);
    __half h[4];
    h[0] = __float2half(acc.x * inv);
    h[1] = __float2half(acc.y * inv);
    h[2] = __float2half(acc.z * inv);
    h[3] = __float2half(acc.w * inv);
    *(uint2*)(g_hxh + (size_t)c * DD + t * 4) = *(const uint2*)h;
}

// ---------------- weight prep (merged) ----------------
__global__ void k_prep(const float* __restrict__ Wp, const float* __restrict__ W1) {
    int i = blockIdx.x * blockDim.x + threadIdx.x;
    if (i < DD * DD) {
        int n = i >> 8, k = i & 255;
        g_wph[n * DD + k] = __float2half(Wp[k * DD + n]);
    }
    if (i < NH * 128 * 64) {
        int h = i >> 13;
        int n = (i >> 6) & 127;
        int k = i & 63;
        g_w1h[i] = __float2half(W1[h * 8192 + k * 128 + n]);
    }
}

// ---------------- fused GEMM + MLP (3-stage cp.async) ----------------
#define ASTR 40
#define BUFB 20480
#define XSTR 136
#define FUSED_SMEM 69632
__global__ void __launch_bounds__(256, 2) k_gemm_fused(const float* __restrict__ xcl,
                                                       const float* __restrict__ bp,
                                                       const float* __restrict__ b1,
                                                       const float* __restrict__ W2,
                                                       const float* __restrict__ b2,
                                                       float* __restrict__ xc) {
    extern __shared__ char dyn[];
    __shared__ float s_b1[2][128], s_w2[2][128];
    int tid = threadIdx.x;
    int lane = tid & 31, wid = tid >> 5;
    int g = lane >> 2, t = lane & 3;
    int wm = wid >> 1, wn = wid & 1;
    int bm = blockIdx.y * 128, bn = blockIdx.x * 128;
    int hd = blockIdx.x * 2;

    if (tid < 256) {
        int hh = tid >> 7, c = tid & 127;
        s_b1[hh][c] = b1[(hd + hh) * 128 + c];
        s_w2[hh][c] = W2[(hd + hh) * 128 + c];
    }

    float acc[2][8][4];
#pragma unroll
    for (int a = 0; a < 2; a++)
#pragma unroll
        for (int b = 0; b < 8; b++)
#pragma unroll
            for (int c = 0; c < 4; c++) acc[a][b][c] = 0.f;

    int lr = tid >> 1, lh = tid & 1;
    int msafe = min(bm + lr, NC - 1);
    int nrow = bn + lr;
    uint32_t so = (uint32_t)(lr * ASTR + lh * 16) * 2;
    uint32_t sbase = smem_u32(dyn);

    auto stage = [&](int buf, int kc) {
        uint32_t sa = sbase + buf * BUFB + so;
        const char* gAh = (const char*)(g_hxh + (size_t)msafe * DD + kc * 32 + lh * 16);
        const char* gBh = (const char*)(g_wph + (size_t)nrow * DD + kc * 32 + lh * 16);
        cp_async16(sa,             gAh);  cp_async16(sa + 16,         gAh + 16);
        cp_async16(sa + 10240,     gBh);  cp_async16(sa + 10240 + 16, gBh + 16);
    };

    int a_row = wm * 32 + (lane & 7) + ((lane >> 3) & 1) * 8;
    int a_col = (lane >> 4) * 8;
    int b_row = wn * 64 + (lane & 7) + ((lane >= 16) ? 8 : 0);
    int b_col = ((lane >> 3) & 1) * 8;

    stage(0, 0); cp_commit();
    stage(1, 1); cp_commit();
    for (int kc = 0; kc < 8; kc++) {
        if (kc < 7) cp_wait<1>(); else cp_wait<0>();
        __syncthreads();
        if (kc + 2 < 8) { stage((kc + 2) % 3, kc + 2); cp_commit(); }
        uint32_t sbuf = sbase + (kc % 3) * BUFB;
#pragma unroll
        for (int ks = 0; ks < 2; ks++) {
            int kb0 = ks * 16;
            uint32_t ah[2][4];
#pragma unroll
            for (int mi = 0; mi < 2; mi++) {
                uint32_t ao = (uint32_t)((a_row + mi * 16) * ASTR + a_col + kb0) * 2;
                ldsm_x4(ah[mi], sbuf + ao);
            }
#pragma unroll
            for (int p = 0; p < 4; p++) {
                uint32_t bo = (uint32_t)((b_row + p * 16) * ASTR + b_col + kb0) * 2;
                uint32_t bh4[4];
                ldsm_x4(bh4, sbuf + 10240 + bo);
#pragma unroll
                for (int mi = 0; mi < 2; mi++) {
                    mma_f16(acc[mi][2 * p],     ah[mi], &bh4[0]);
                    mma_f16(acc[mi][2 * p + 1], ah[mi], &bh4[2]);
                }
            }
        }
    }
    __syncthreads();

    // ---- epilogue ----
    __half* xcH = (__half*)dyn;
    __half* xcL = xcH + 128 * XSTR;
#pragma unroll
    for (int mi = 0; mi < 2; mi++) {
        int rr0 = wm * 32 + mi * 16 + g;
        int rr1 = rr0 + 8;
        int r0 = bm + rr0, r1 = bm + rr1;
#pragma unroll
        for (int ni = 0; ni < 8; ni++) {
            int colrel = wn * 64 + ni * 8 + 2 * t;
            int col = bn + colrel;
            float2 bpv = *(const float2*)(bp + col);
            float o0 = fmaxf(acc[mi][ni][0] + bpv.x, 0.f);
            float o1 = fmaxf(acc[mi][ni][1] + bpv.y, 0.f);
            float o2 = fmaxf(acc[mi][ni][2] + bpv.x, 0.f);
            float o3 = fmaxf(acc[mi][ni][3] + bpv.y, 0.f);
            if (r0 < NC) {
                float2 xv = *(const float2*)(xcl + (size_t)r0 * DD + col);
                o0 += xv.x; o1 += xv.y;
                *(float2*)(xc + (size_t)r0 * DD + col) = make_float2(o0, o1);
            }
            if (r1 < NC) {
                float2 xv = *(const float2*)(xcl + (size_t)r1 * DD + col);
                o2 += xv.x; o3 += xv.y;
                *(float2*)(xc + (size_t)r1 * DD + col) = make_float2(o2, o3);
            }
            __half l0, l1, l2, l3;
            uint32_t h0 = pack_split(o0, &l0), h1 = pack_split(o1, &l1);
            uint32_t h2 = pack_split(o2, &l2), h3 = pack_split(o3, &l3);
            *(uint32_t*)&xcH[rr0 * XSTR + colrel] = h0 | (h1 << 16);
            *(uint32_t*)&xcH[rr1 * XSTR + colrel] = h2 | (h3 << 16);
            uint16_t ul0 = *(const uint16_t*)&l0, ul1 = *(const uint16_t*)&l1;
            uint16_t ul2 = *(const uint16_t*)&l2, ul3 = *(const uint16_t*)&l3;
            *(uint32_t*)&xcL[rr0 * XSTR + colrel] = (uint32_t)ul0 | ((uint32_t)ul1 << 16);
            *(uint32_t*)&xcL[rr1 * XSTR + colrel] = (uint32_t)ul2 | ((uint32_t)ul3 << 16);
        }
    }
    __syncthreads();

    // ---- phase 2: per-head MLP ----
    int h = hd + wn;
    uint32_t mh[2][4][4], ml[2][4][4];
#pragma unroll
    for (int mi = 0; mi < 2; mi++)
#pragma unroll
        for (int ks = 0; ks < 4; ks++) {
            int rb = (wm * 32 + mi * 16 + g) * XSTR + wn * 64 + ks * 16 + 2 * t;
            mh[mi][ks][0] = *(const uint32_t*)&xcH[rb];
            mh[mi][ks][1] = *(const uint32_t*)&xcH[rb + 8 * XSTR];
            mh[mi][ks][2] = *(const uint32_t*)&xcH[rb + 8];
            mh[mi][ks][3] = *(const uint32_t*)&xcH[rb + 8 * XSTR + 8];
            ml[mi][ks][0] = *(const uint32_t*)&xcL[rb];
            ml[mi][ks][1] = *(const uint32_t*)&xcL[rb + 8 * XSTR];
            ml[mi][ks][2] = *(const uint32_t*)&xcL[rb + 8];
            ml[mi][ks][3] = *(const uint32_t*)&xcL[rb + 8 * XSTR + 8];
        }
    float s0[2] = {0.f, 0.f}, s1[2] = {0.f, 0.f};
#pragma unroll
    for (int nj = 0; nj < 16; nj++) {
        float a2[2][4] = {{0.f,0.f,0.f,0.f},{0.f,0.f,0.f,0.f}};
        int n = nj * 8 + g;
#pragma unroll
        for (int ks = 0; ks < 4; ks++) {
            int koff = h * 8192 + n * 64 + ks * 16 + 2 * t;
            uint32_t bh[2];
            bh[0] = *(const uint32_t*)&g_w1h[koff];
            bh[1] = *(const uint32_t*)&g_w1h[koff + 8];
#pragma unroll
            for (int mi = 0; mi < 2; mi++) {
                mma_f16(a2[mi], mh[mi][ks], bh);
                mma_f16(a2[mi], ml[mi][ks], bh);
            }
        }
        int col = nj * 8 + 2 * t;
        float w0 = s_w2[wn][col], w1v = s_w2[wn][col + 1];
        float q0 = s_b1[wn][col], q1 = s_b1[wn][col + 1];
#pragma unroll
        for (int mi = 0; mi < 2; mi++) {
            s0[mi] += fmaxf(a2[mi][0] + q0, 0.f) * w0 + fmaxf(a2[mi][1] + q1, 0.f) * w1v;
            s1[mi] += fmaxf(a2[mi][2] + q0, 0.f) * w0 + fmaxf(a2[mi][3] + q1, 0.f) * w1v;
        }
    }
#pragma unroll
    for (int mi = 0; mi < 2; mi++) {
        s0[mi] += __shfl_xor_sync(0xFFFFFFFFu, s0[mi], 1);
        s0[mi] += __shfl_xor_sync(0xFFFFFFFFu, s0[mi], 2);
        s1[mi] += __shfl_xor_sync(0xFFFFFFFFu, s1[mi], 1);
        s1[mi] += __shfl_xor_sync(0xFFFFFFFFu, s1[mi], 2);
    }
    if (t == 0) {
        float b2h = __ldg(b2 + h);
#pragma unroll
        for (int mi = 0; mi < 2; mi++) {
            int r0 = bm + wm * 32 + mi * 16 + g;
            if (r0 < NC) g_score[r0 * NH + h] = s0[mi] + b2h;
            if (r0 + 8 < NC) g_score[(r0 + 8) * NH + h] = s1[mi] + b2h;
        }
    }
}

// ---------------- segment softmax ----------------
__global__ void k_segmax() {
    int i = blockIdx.x * blockDim.x + threadIdx.x;
    if (i >= NC * NH) return;
    int c = i >> 2, h = i & 3;
    atomicMax(&g_mxu[g_cb[c] * NH + h], f2u_ord(g_score[i]));
}
__global__ void k_segsum() {
    int i = blockIdx.x * blockDim.x + threadIdx.x;
    if (i >= NC * NH) return;
    int c = i >> 2, h = i & 3;
    int b = g_cb[c];
    float e = expf(g_score[i] - u2f_ord(g_mxu[b * NH + h]));
    g_score[i] = e;
    atomicAdd(&g_den[b * NH + h], e);
}
__global__ void k_alpha(float* __restrict__ alpha_out) {
    int i = blockIdx.x * blockDim.x + threadIdx.x;
    if (i >= NC * NH) return;
    int c = i >> 2, h = i & 3;
    alpha_out[i] = g_score[i] / (g_den[g_cb[c] * NH + h] + 1e-16f);
}

// ---------------- drug_feat segment-sum ----------------
__global__ void k_final(const float* __restrict__ xc, const float* __restrict__ alpha,
                        float* __restrict__ drug) {
    int d = threadIdx.x;
    int hh = d >> 6;
    int c0 = blockIdx.x * 128;
    if (c0 >= NC) return;
    int cend = min(c0 + 128, NC);
    float acc = 0.f;
    int cur = g_cb[c0];
    for (int c = c0; c < cend; c++) {
        int b = g_cb[c];
        if (b != cur) {
            atomicAdd(&drug[(size_t)cur * DD + d], acc);
            acc = 0.f; cur = b;
        }
        acc += xc[(size_t)c * DD + d] * alpha[c * NH + hh];
    }
    atomicAdd(&drug[(size_t)cur * DD + d], acc);
}

// ---------------- launcher ----------------
extern "C" void kernel_launch(void* const* d_in, const int* in_sizes, int n_in,
                              void* d_out, int out_size) {
    const float* x    = (const float*)d_in[0];
    const float* xcl  = (const float*)d_in[1];
    const float* Wp   = (const float*)d_in[2];
    const float* bp   = (const float*)d_in[3];
    const float* W1   = (const float*)d_in[4];
    const float* b1   = (const float*)d_in[5];
    const float* W2   = (const float*)d_in[6];
    const float* b2   = (const float*)d_in[7];
    const void*  a2c  = d_in[8];
    const void*  cb   = d_in[9];

    float* out  = (float*)d_out;
    float* drug = out;
    float* xc   = out + (size_t)NB * DD;
    float* alph = out + (size_t)NB * DD + (size_t)NC * DD;

    cudaFuncSetAttribute(k_gemm_fused, cudaFuncAttributeMaxDynamicSharedMemorySize, FUSED_SMEM);

    k_initdet<<<(NB * DD + 255) / 256, 256>>>(drug, (const long long*)a2c);
    k_hist_cvt<<<(NE + 255) / 256, 256>>>(a2c, cb);
    int nscan = (NC + 2047) / 2048;
    k_scan_a<<<nscan, 256>>>();
    k_scan_b<<<1, 32>>>(nscan);
    k_scan_c<<<(NC + 255) / 256, 256>>>();
    k_fill<<<(NE + 255) / 256, 256>>>(a2c);
    k_agg<<<(NC + 3) / 4, 256>>>(x);
    k_prep<<<(DD * DD + 255) / 256, 256>>>(Wp, W1);
    {
        dim3 g(2, (NC + 127) / 128);
        k_gemm_fused<<<g, 256, FUSED_SMEM>>>(xcl, bp, b1, W2, b2, xc);
    }
    k_segmax<<<(NC * NH + 255) / 256, 256>>>();
    k_segsum<<<(NC * NH + 255) / 256, 256>>>();
    k_alpha<<<(NC * NH + 255) / 256, 256>>>(alph);
    k_final<<<(NC + 127) / 128, 256>>>(xc, alph, drug);
}

// round 14
// speedup vs baseline: 1.0234x; 1.0234x over previous
#include <cuda_runtime.h>
#include <cuda_fp16.h>
#include <math.h>
#include <stdint.h>

#define NA 500000
#define NC 250000
#define NE 1000000
#define NB 2048
#define DD 256
#define NH 4

// ---------------- scratch ----------------
__device__ __align__(16) __half g_hxh[(size_t)NC * DD];
__device__ __align__(16) __half g_wph[DD * DD];       // Wp^T fp16 [N][K]
__device__ __align__(16) __half g_w1h[NH * 128 * 64]; // W1^T fp16 [h][n][k]
__device__ int      g_cb[NC];
__device__ int      g_cnt[NC];
__device__ int      g_off[NC + 1];
__device__ int      g_fill[NC];
__device__ int      g_csr[NE];
__device__ int      g_part[256];
__device__ float    g_score[NC * NH];
__device__ unsigned g_mxu[NB * NH];
__device__ float    g_den[NB * NH];
__device__ int      g_is32;

// ---------------- PTX helpers ----------------
__device__ __forceinline__ void mma_f16(float* c, const uint32_t* a, const uint32_t* b) {
    asm volatile(
        "mma.sync.aligned.m16n8k16.row.col.f32.f16.f16.f32 "
        "{%0,%1,%2,%3}, {%4,%5,%6,%7}, {%8,%9}, {%0,%1,%2,%3};"
        : "+f"(c[0]), "+f"(c[1]), "+f"(c[2]), "+f"(c[3])
        : "r"(a[0]), "r"(a[1]), "r"(a[2]), "r"(a[3]), "r"(b[0]), "r"(b[1]));
}
__device__ __forceinline__ void ldsm_x4(uint32_t* r, uint32_t saddr) {
    asm volatile("ldmatrix.sync.aligned.m8n8.x4.shared.b16 {%0,%1,%2,%3}, [%4];"
        : "=r"(r[0]), "=r"(r[1]), "=r"(r[2]), "=r"(r[3]) : "r"(saddr));
}
__device__ __forceinline__ uint32_t smem_u32(const void* p) {
    uint32_t a;
    asm("{ .reg .u64 t; cvta.to.shared.u64 t, %1; cvt.u32.u64 %0, t; }" : "=r"(a) : "l"(p));
    return a;
}
__device__ __forceinline__ void cp_async16(uint32_t sa, const void* g) {
    asm volatile("cp.async.cg.shared.global [%0], [%1], 16;" :: "r"(sa), "l"(g));
}
__device__ __forceinline__ void cp_commit() { asm volatile("cp.async.commit_group;"); }
template <int N>
__device__ __forceinline__ void cp_wait() { asm volatile("cp.async.wait_group %0;" :: "n"(N)); }

__device__ __forceinline__ unsigned f2u_ord(float f) {
    unsigned u = __float_as_uint(f);
    return (u & 0x80000000u) ? ~u : (u | 0x80000000u);
}
__device__ __forceinline__ float u2f_ord(unsigned u) {
    return (u & 0x80000000u) ? __uint_as_float(u ^ 0x80000000u) : __uint_as_float(~u);
}
__device__ __forceinline__ int clampi(int v, int lo, int hi) {
    return v < lo ? lo : (v > hi ? hi : v);
}
__device__ __forceinline__ uint32_t pack_split(float f, __half* lo) {
    __half h = __float2half(f);
    *lo = __float2half(f - __half2float(h));
    return (uint32_t)*(const uint16_t*)&h;
}
__device__ __forceinline__ int idx_at(const void* p, int i) {
    return g_is32 ? ((const int*)p)[i] : (int)(((const long long*)p)[i]);
}

// ---------------- init (+detect in block 0) ----------------
__global__ void k_initdet(float* __restrict__ drug, const long long* __restrict__ a2c) {
    int i = blockIdx.x * blockDim.x + threadIdx.x;
    if (blockIdx.x == 0) {
        __shared__ int s;
        if (threadIdx.x == 0) s = 0;
        __syncthreads();
        long long v = a2c[threadIdx.x];
        if (v < 0 || v >= 0x80000000LL) atomicOr(&s, 1);
        __syncthreads();
        if (threadIdx.x == 0) g_is32 = s;
    }
    if (i < NB * DD) drug[i] = 0.f;
    if (i < NC) { g_cnt[i] = 0; g_fill[i] = 0; }
    if (i < NB * NH) { g_den[i] = 0.f; g_mxu[i] = f2u_ord(-3.0e38f); }
}

// ---------------- histogram + cb convert ----------------
__global__ void k_hist_cvt(const void* __restrict__ a2c, const void* __restrict__ cb) {
    int i = blockIdx.x * blockDim.x + threadIdx.x;
    if (i < NC) g_cb[i] = clampi(idx_at(cb, i), 0, NB - 1);
    if (i < NE) atomicAdd(&g_cnt[clampi(idx_at(a2c, NE + i), 0, NC - 1)], 1);
}

// ---------------- scan ----------------
__global__ void k_scan_a() {
    __shared__ int sums[256];
    int tid = threadIdx.x;
    int base = blockIdx.x * 2048 + tid * 8;
    int pre[8]; int s = 0;
#pragma unroll
    for (int j = 0; j < 8; j++) {
        int idx = base + j;
        int v = (idx < NC) ? g_cnt[idx] : 0;
        pre[j] = s; s += v;
    }
    sums[tid] = s;
    __syncthreads();
    for (int off = 1; off < 256; off <<= 1) {
        int t = (tid >= off) ? sums[tid - off] : 0;
        __syncthreads();
        sums[tid] += t;
        __syncthreads();
    }
    int excl = (tid == 0) ? 0 : sums[tid - 1];
#pragma unroll
    for (int j = 0; j < 8; j++) {
        int idx = base + j;
        if (idx < NC) g_off[idx] = excl + pre[j];
    }
    if (tid == 255) g_part[blockIdx.x] = sums[255];
}
// parallel exclusive scan over <=128 block partials (Hillis-Steele in smem)
__global__ void k_scan_b(int nb) {
    __shared__ int sums[128];
    int tid = threadIdx.x;
    int v = (tid < nb) ? g_part[tid] : 0;
    sums[tid] = v;
    __syncthreads();
    for (int off = 1; off < 128; off <<= 1) {
        int t = (tid >= off) ? sums[tid - off] : 0;
        __syncthreads();
        sums[tid] += t;
        __syncthreads();
    }
    if (tid < nb) g_part[tid] = (tid == 0) ? 0 : sums[tid - 1];
}
__global__ void k_scan_c() {
    int i = blockIdx.x * blockDim.x + threadIdx.x;
    if (i < NC) g_off[i] += g_part[i >> 11];
}

// ---------------- CSR fill ----------------
__global__ void k_fill(const void* __restrict__ a2c) {
    int i = blockIdx.x * blockDim.x + threadIdx.x;
    if (i >= NE) return;
    int c = clampi(idx_at(a2c, NE + i), 0, NC - 1);
    int r = clampi(idx_at(a2c, i), 0, NA - 1);
    int p = g_off[c] + atomicAdd(&g_fill[c], 1);
    if (p >= 0 && p < NE) g_csr[p] = r;
}

// ---------------- gather + mean -> fp16 (1 clique / 64-thread block, R12 form) ----------------
__global__ void k_agg(const float* __restrict__ x) {
    int c = blockIdx.x;
    int t = threadIdx.x;  // 0..63
    int deg = g_cnt[c];
    int st  = g_off[c];
    float4 acc = make_float4(0.f, 0.f, 0.f, 0.f);
    int e = 0;
    for (; e + 2 <= deg; e += 2) {
        int r0 = g_csr[st + e], r1 = g_csr[st + e + 1];
        float4 a = ((const float4*)(x + (size_t)r0 * DD))[t];
        float4 b = ((const float4*)(x + (size_t)r1 * DD))[t];
        acc.x += a.x + b.x; acc.y += a.y + b.y;
        acc.z += a.z + b.z; acc.w += a.w + b.w;
    }
    if (e < deg) {
        int r0 = g_csr[st + e];
        float4 a = ((const float4*)(x + (size_t)r0 * DD))[t];
        acc.x += a.x; acc.y += a.y; acc.z += a.z; acc.w += a.w;
    }
    float inv = 1.f / (float)max(deg, 1);
    __half h[4];
    h[0] = __float2half(acc.x * inv);
    h[1] = __float2half(acc.y * inv);
    h[2] = __float2half(acc.z * inv);
    h[3] = __float2half(acc.w * inv);
    *(uint2*)(g_hxh + (size_t)c * DD + t * 4) = *(const uint2*)h;
}

// ---------------- weight prep (merged) ----------------
__global__ void k_prep(const float* __restrict__ Wp, const float* __restrict__ W1) {
    int i = blockIdx.x * blockDim.x + threadIdx.x;
    if (i < DD * DD) {
        int n = i >> 8, k = i & 255;
        g_wph[n * DD + k] = __float2half(Wp[k * DD + n]);
    }
    if (i < NH * 128 * 64) {
        int h = i >> 13;
        int n = (i >> 6) & 127;
        int k = i & 63;
        g_w1h[i] = __float2half(W1[h * 8192 + k * 128 + n]);
    }
}

// ---------------- fused GEMM + MLP (3-stage cp.async) ----------------
#define ASTR 40
#define BUFB 20480
#define XSTR 136
#define FUSED_SMEM 69632
__global__ void __launch_bounds__(256, 2) k_gemm_fused(const float* __restrict__ xcl,
                                                       const float* __restrict__ bp,
                                                       const float* __restrict__ b1,
                                                       const float* __restrict__ W2,
                                                       const float* __restrict__ b2,
                                                       float* __restrict__ xc) {
    extern __shared__ char dyn[];
    __shared__ float s_b1[2][128], s_w2[2][128];
    int tid = threadIdx.x;
    int lane = tid & 31, wid = tid >> 5;
    int g = lane >> 2, t = lane & 3;
    int wm = wid >> 1, wn = wid & 1;
    int bm = blockIdx.y * 128, bn = blockIdx.x * 128;
    int hd = blockIdx.x * 2;

    if (tid < 256) {
        int hh = tid >> 7, c = tid & 127;
        s_b1[hh][c] = b1[(hd + hh) * 128 + c];
        s_w2[hh][c] = W2[(hd + hh) * 128 + c];
    }

    float acc[2][8][4];
#pragma unroll
    for (int a = 0; a < 2; a++)
#pragma unroll
        for (int b = 0; b < 8; b++)
#pragma unroll
            for (int c = 0; c < 4; c++) acc[a][b][c] = 0.f;

    int lr = tid >> 1, lh = tid & 1;
    int msafe = min(bm + lr, NC - 1);
    int nrow = bn + lr;
    uint32_t so = (uint32_t)(lr * ASTR + lh * 16) * 2;
    uint32_t sbase = smem_u32(dyn);

    auto stage = [&](int buf, int kc) {
        uint32_t sa = sbase + buf * BUFB + so;
        const char* gAh = (const char*)(g_hxh + (size_t)msafe * DD + kc * 32 + lh * 16);
        const char* gBh = (const char*)(g_wph + (size_t)nrow * DD + kc * 32 + lh * 16);
        cp_async16(sa,             gAh);  cp_async16(sa + 16,         gAh + 16);
        cp_async16(sa + 10240,     gBh);  cp_async16(sa + 10240 + 16, gBh + 16);
    };

    int a_row = wm * 32 + (lane & 7) + ((lane >> 3) & 1) * 8;
    int a_col = (lane >> 4) * 8;
    int b_row = wn * 64 + (lane & 7) + ((lane >= 16) ? 8 : 0);
    int b_col = ((lane >> 3) & 1) * 8;

    stage(0, 0); cp_commit();
    stage(1, 1); cp_commit();
    for (int kc = 0; kc < 8; kc++) {
        if (kc < 7) cp_wait<1>(); else cp_wait<0>();
        __syncthreads();
        if (kc + 2 < 8) { stage((kc + 2) % 3, kc + 2); cp_commit(); }
        uint32_t sbuf = sbase + (kc % 3) * BUFB;
#pragma unroll
        for (int ks = 0; ks < 2; ks++) {
            int kb0 = ks * 16;
            uint32_t ah[2][4];
#pragma unroll
            for (int mi = 0; mi < 2; mi++) {
                uint32_t ao = (uint32_t)((a_row + mi * 16) * ASTR + a_col + kb0) * 2;
                ldsm_x4(ah[mi], sbuf + ao);
            }
#pragma unroll
            for (int p = 0; p < 4; p++) {
                uint32_t bo = (uint32_t)((b_row + p * 16) * ASTR + b_col + kb0) * 2;
                uint32_t bh4[4];
                ldsm_x4(bh4, sbuf + 10240 + bo);
#pragma unroll
                for (int mi = 0; mi < 2; mi++) {
                    mma_f16(acc[mi][2 * p],     ah[mi], &bh4[0]);
                    mma_f16(acc[mi][2 * p + 1], ah[mi], &bh4[2]);
                }
            }
        }
    }
    __syncthreads();

    // ---- epilogue ----
    __half* xcH = (__half*)dyn;
    __half* xcL = xcH + 128 * XSTR;
#pragma unroll
    for (int mi = 0; mi < 2; mi++) {
        int rr0 = wm * 32 + mi * 16 + g;
        int rr1 = rr0 + 8;
        int r0 = bm + rr0, r1 = bm + rr1;
#pragma unroll
        for (int ni = 0; ni < 8; ni++) {
            int colrel = wn * 64 + ni * 8 + 2 * t;
            int col = bn + colrel;
            float2 bpv = *(const float2*)(bp + col);
            float o0 = fmaxf(acc[mi][ni][0] + bpv.x, 0.f);
            float o1 = fmaxf(acc[mi][ni][1] + bpv.y, 0.f);
            float o2 = fmaxf(acc[mi][ni][2] + bpv.x, 0.f);
            float o3 = fmaxf(acc[mi][ni][3] + bpv.y, 0.f);
            if (r0 < NC) {
                float2 xv = *(const float2*)(xcl + (size_t)r0 * DD + col);
                o0 += xv.x; o1 += xv.y;
                *(float2*)(xc + (size_t)r0 * DD + col) = make_float2(o0, o1);
            }
            if (r1 < NC) {
                float2 xv = *(const float2*)(xcl + (size_t)r1 * DD + col);
                o2 += xv.x; o3 += xv.y;
                *(float2*)(xc + (size_t)r1 * DD + col) = make_float2(o2, o3);
            }
            __half l0, l1, l2, l3;
            uint32_t h0 = pack_split(o0, &l0), h1 = pack_split(o1, &l1);
            uint32_t h2 = pack_split(o2, &l2), h3 = pack_split(o3, &l3);
            *(uint32_t*)&xcH[rr0 * XSTR + colrel] = h0 | (h1 << 16);
            *(uint32_t*)&xcH[rr1 * XSTR + colrel] = h2 | (h3 << 16);
            uint16_t ul0 = *(const uint16_t*)&l0, ul1 = *(const uint16_t*)&l1;
            uint16_t ul2 = *(const uint16_t*)&l2, ul3 = *(const uint16_t*)&l3;
            *(uint32_t*)&xcL[rr0 * XSTR + colrel] = (uint32_t)ul0 | ((uint32_t)ul1 << 16);
            *(uint32_t*)&xcL[rr1 * XSTR + colrel] = (uint32_t)ul2 | ((uint32_t)ul3 << 16);
        }
    }
    __syncthreads();

    // ---- phase 2: per-head MLP ----
    int h = hd + wn;
    uint32_t mh[2][4][4], ml[2][4][4];
#pragma unroll
    for (int mi = 0; mi < 2; mi++)
#pragma unroll
        for (int ks = 0; ks < 4; ks++) {
            int rb = (wm * 32 + mi * 16 + g) * XSTR + wn * 64 + ks * 16 + 2 * t;
            mh[mi][ks][0] = *(const uint32_t*)&xcH[rb];
            mh[mi][ks][1] = *(const uint32_t*)&xcH[rb + 8 * XSTR];
            mh[mi][ks][2] = *(const uint32_t*)&xcH[rb + 8];
            mh[mi][ks][3] = *(const uint32_t*)&xcH[rb + 8 * XSTR + 8];
            ml[mi][ks][0] = *(const uint32_t*)&xcL[rb];
            ml[mi][ks][1] = *(const uint32_t*)&xcL[rb + 8 * XSTR];
            ml[mi][ks][2] = *(const uint32_t*)&xcL[rb + 8];
            ml[mi][ks][3] = *(const uint32_t*)&xcL[rb + 8 * XSTR + 8];
        }
    float s0[2] = {0.f, 0.f}, s1[2] = {0.f, 0.f};
#pragma unroll
    for (int nj = 0; nj < 16; nj++) {
        float a2[2][4] = {{0.f,0.f,0.f,0.f},{0.f,0.f,0.f,0.f}};
        int n = nj * 8 + g;
#pragma unroll
        for (int ks = 0; ks < 4; ks++) {
            int koff = h * 8192 + n * 64 + ks * 16 + 2 * t;
            uint32_t bh[2];
            bh[0] = *(const uint32_t*)&g_w1h[koff];
            bh[1] = *(const uint32_t*)&g_w1h[koff + 8];
#pragma unroll
            for (int mi = 0; mi < 2; mi++) {
                mma_f16(a2[mi], mh[mi][ks], bh);
                mma_f16(a2[mi], ml[mi][ks], bh);
            }
        }
        int col = nj * 8 + 2 * t;
        float w0 = s_w2[wn][col], w1v = s_w2[wn][col + 1];
        float q0 = s_b1[wn][col], q1 = s_b1[wn][col + 1];
#pragma unroll
        for (int mi = 0; mi < 2; mi++) {
            s0[mi] += fmaxf(a2[mi][0] + q0, 0.f) * w0 + fmaxf(a2[mi][1] + q1, 0.f) * w1v;
            s1[mi] += fmaxf(a2[mi][2] + q0, 0.f) * w0 + fmaxf(a2[mi][3] + q1, 0.f) * w1v;
        }
    }
#pragma unroll
    for (int mi = 0; mi < 2; mi++) {
        s0[mi] += __shfl_xor_sync(0xFFFFFFFFu, s0[mi], 1);
        s0[mi] += __shfl_xor_sync(0xFFFFFFFFu, s0[mi], 2);
        s1[mi] += __shfl_xor_sync(0xFFFFFFFFu, s1[mi], 1);
        s1[mi] += __shfl_xor_sync(0xFFFFFFFFu, s1[mi], 2);
    }
    if (t == 0) {
        float b2h = __ldg(b2 + h);
#pragma unroll
        for (int mi = 0; mi < 2; mi++) {
            int r0 = bm + wm * 32 + mi * 16 + g;
            if (r0 < NC) g_score[r0 * NH + h] = s0[mi] + b2h;
            if (r0 + 8 < NC) g_score[(r0 + 8) * NH + h] = s1[mi] + b2h;
        }
    }
}

// ---------------- segment softmax ----------------
__global__ void k_segmax() {
    int i = blockIdx.x * blockDim.x + threadIdx.x;
    if (i >= NC * NH) return;
    int c = i >> 2, h = i & 3;
    atomicMax(&g_mxu[g_cb[c] * NH + h], f2u_ord(g_score[i]));
}
__global__ void k_segsum() {
    int i = blockIdx.x * blockDim.x + threadIdx.x;
    if (i >= NC * NH) return;
    int c = i >> 2, h = i & 3;
    int b = g_cb[c];
    float e = expf(g_score[i] - u2f_ord(g_mxu[b * NH + h]));
    g_score[i] = e;
    atomicAdd(&g_den[b * NH + h], e);
}
__global__ void k_alpha(float* __restrict__ alpha_out) {
    int i = blockIdx.x * blockDim.x + threadIdx.x;
    if (i >= NC * NH) return;
    int c = i >> 2, h = i & 3;
    alpha_out[i] = g_score[i] / (g_den[g_cb[c] * NH + h] + 1e-16f);
}

// ---------------- drug_feat segment-sum ----------------
__global__ void k_final(const float* __restrict__ xc, const float* __restrict__ alpha,
                        float* __restrict__ drug) {
    int d = threadIdx.x;
    int hh = d >> 6;
    int c0 = blockIdx.x * 128;
    if (c0 >= NC) return;
    int cend = min(c0 + 128, NC);
    float acc = 0.f;
    int cur = g_cb[c0];
    for (int c = c0; c < cend; c++) {
        int b = g_cb[c];
        if (b != cur) {
            atomicAdd(&drug[(size_t)cur * DD + d], acc);
            acc = 0.f; cur = b;
        }
        acc += xc[(size_t)c * DD + d] * alpha[c * NH + hh];
    }
    atomicAdd(&drug[(size_t)cur * DD + d], acc);
}

// ---------------- launcher ----------------
extern "C" void kernel_launch(void* const* d_in, const int* in_sizes, int n_in,
                              void* d_out, int out_size) {
    const float* x    = (const float*)d_in[0];
    const float* xcl  = (const float*)d_in[1];
    const float* Wp   = (const float*)d_in[2];
    const float* bp   = (const float*)d_in[3];
    const float* W1   = (const float*)d_in[4];
    const float* b1   = (const float*)d_in[5];
    const float* W2   = (const float*)d_in[6];
    const float* b2   = (const float*)d_in[7];
    const void*  a2c  = d_in[8];
    const void*  cb   = d_in[9];

    float* out  = (float*)d_out;
    float* drug = out;
    float* xc   = out + (size_t)NB * DD;
    float* alph = out + (size_t)NB * DD + (size_t)NC * DD;

    cudaFuncSetAttribute(k_gemm_fused, cudaFuncAttributeMaxDynamicSharedMemorySize, FUSED_SMEM);

    k_initdet<<<(NB * DD + 255) / 256, 256>>>(drug, (const long long*)a2c);
    k_hist_cvt<<<(NE + 255) / 256, 256>>>(a2c, cb);
    int nscan = (NC + 2047) / 2048;
    k_scan_a<<<nscan, 256>>>();
    k_scan_b<<<1, 128>>>(nscan);
    k_scan_c<<<(NC + 255) / 256, 256>>>();
    k_fill<<<(NE + 255) / 256, 256>>>(a2c);
    k_agg<<<NC, 64>>>(x);
    k_prep<<<(DD * DD + 255) / 256, 256>>>(Wp, W1);
    {
        dim3 g(2, (NC + 127) / 128);
        k_gemm_fused<<<g, 256, FUSED_SMEM>>>(xcl, bp, b1, W2, b2, xc);
    }
    k_segmax<<<(NC * NH + 255) / 256, 256>>>();
    k_segsum<<<(NC * NH + 255) / 256, 256>>>();
    k_alpha<<<(NC * NH + 255) / 256, 256>>>(alph);
    k_final<<<(NC + 127) / 128, 256>>>(xc, alph, drug);
}